// round 16
// baseline (speedup 1.0000x reference)
#include <cuda_runtime.h>
#include <math.h>

#define BATCH 2048
#define NC    9605
#define NL    8
#define MAXWL 512
#define NTHR  256
#define NBLD  32           // dedicated builder blocks (exit after building)
#define RPB   2            // rows per block (packs grid into one wave)
#define NCAND (3 * NTHR)   // 768-key per-thread top-3 union
#define CAP   2048         // level-0 bins / fallback hist / candidate buffer

__device__ int           g_wl_count;   // all zero-init; reset by last row block
__device__ int           g_wl_idx[MAXWL];
__device__ unsigned char g_wl_mask[MAXWL];
__device__ float         g_row_val[BATCH];
__device__ int           g_done;
__device__ int           g_wl_done;
__device__ int           g_wl_ready;
__device__ int           g_badint, g_badf;
__device__ int           g_sniff_done;
__device__ int           g_mode_ready;

__device__ __forceinline__ float sigmoidf_(float v) {
    return 1.0f / (1.0f + expf(-v));   // v = -1e30 -> 0 (correct)
}
__device__ __forceinline__ unsigned f2k(unsigned u) {          // monotone float->uint
    return (u & 0x80000000u) ? ~u : (u | 0x80000000u);
}
__device__ __forceinline__ float k2f(unsigned k) {
    return (k & 0x80000000u) ? __uint_as_float(k ^ 0x80000000u)
                             : __uint_as_float(~k);
}
// branchless sorted top-3 insert (6 ops, no branches)
__device__ __forceinline__ void top3_ins(float v, float& t0, float& t1, float& t2) {
    float m0  = fmaxf(t0, v);
    float mn0 = fminf(t0, v);
    float m1  = fmaxf(t1, mn0);
    float mn1 = fminf(t1, mn0);
    t2 = fmaxf(t2, mn1);
    t0 = m0; t1 = m1;
}

// pick8: suffix-select over 2048 bins (thread t owns bins [8t,8t+8)).
__device__ __forceinline__ void pick8(const unsigned* __restrict__ hist,
                                      unsigned* __restrict__ wsum,
                                      unsigned* __restrict__ sb,
                                      unsigned* __restrict__ sw,
                                      unsigned* __restrict__ sc,
                                      unsigned want, int tid) {
    unsigned v[8];
    unsigned tot = 0;
#pragma unroll
    for (int i = 0; i < 8; ++i) { v[i] = hist[tid * 8 + i]; tot += v[i]; }
    unsigned incl = tot;
#pragma unroll
    for (int d = 1; d < 32; d <<= 1) {
        unsigned n = __shfl_down_sync(0xffffffffu, incl, d);
        if ((tid & 31) + d < 32) incl += n;
    }
    if ((tid & 31) == 0) wsum[tid >> 5] = incl;
    __syncthreads();
    unsigned above = incl - tot;
#pragma unroll
    for (int w = 0; w < NTHR / 32; ++w)
        if (w > (tid >> 5)) above += wsum[w];
    unsigned suf = above;
#pragma unroll
    for (int j = 7; j >= 0; --j) {
        unsigned nsuf = suf + v[j];
        if (suf < want && want <= nsuf) {
            *sb = (unsigned)(tid * 8 + j); *sw = want - suf; *sc = v[j];
        }
        suf = nsuf;
    }
    __syncthreads();
}

// pick1: suffix-select over <=256 bins (thread t owns bin t). (fallback)
__device__ __forceinline__ void pick1(const unsigned* __restrict__ hist, int nbins,
                                      unsigned* __restrict__ wsum,
                                      unsigned* __restrict__ sb,
                                      unsigned* __restrict__ sw,
                                      unsigned* __restrict__ sc,
                                      unsigned want, int tid) {
    unsigned v = (tid < nbins) ? hist[tid] : 0u;
    unsigned incl = v;
#pragma unroll
    for (int d = 1; d < 32; d <<= 1) {
        unsigned n = __shfl_down_sync(0xffffffffu, incl, d);
        if ((tid & 31) + d < 32) incl += n;
    }
    if ((tid & 31) == 0) wsum[tid >> 5] = incl;
    __syncthreads();
    unsigned above = incl - v;
#pragma unroll
    for (int w = 0; w < NTHR / 32; ++w)
        if (w > (tid >> 5)) above += wsum[w];
    if (above < want && want <= above + v) { *sb = (unsigned)tid; *sw = want - above; *sc = v; }
    __syncthreads();
}

// ---------------------------------------------------------------------------
// Single kernel, grid = NBLD + BATCH/RPB (one full wave).
//  Blocks 0..NBLD-1: dedicated builders (distributed dtype sniff + stripe
//  compaction), then EXIT — off the row critical path.
//  Row blocks: RPB rows each, sequentially. Per row: float4 x4 stream +
//  per-thread top-3; FLATTENED select (one 11-bit histogram over the 768-key
//  union + candidate collect + exact rank-select); conservative validity
//  bound with exact full-histogram fallback; then wl gather + epilogue per
//  row; last row block does the deterministic mean + state reset.
// ---------------------------------------------------------------------------
__global__ void __launch_bounds__(NTHR, 8)
row_kernel(const float* __restrict__ x, const float* __restrict__ y,
           const void* __restrict__ wlraw, float* __restrict__ out) {
    __shared__ unsigned s_keys[NCAND];
    __shared__ unsigned s_big[CAP];               // lvl0 bins / cands / fallback / mean
    __shared__ unsigned s_wsum[NTHR / 32];
    __shared__ float    s_fw[NTHR / 32];
    __shared__ unsigned s_bin, s_want, s_cnt;
    __shared__ unsigned s_ncand, s_selk;
    __shared__ float    s_lmax[NTHR / 32][NL];
    __shared__ float    s_un[NTHR / 32];
    __shared__ unsigned s_pb[NTHR / 32];
    __shared__ int      s_last;

    const int b   = blockIdx.x;
    const int tid = threadIdx.x;

    // ================= builder blocks: build whitelist, exit ===============
    if (b < NBLD) {
        const int NQ    = (NL * NC) / 4;          // safe 4B slots under any dtype
        const int chunk = (NQ + NBLD - 1) / NBLD;
        const int lo    = b * chunk;
        const int hi    = (lo + chunk < NQ) ? lo + chunk : NQ;
        const int*   ip = (const int*)wlraw;
        const float* fp = (const float*)wlraw;
        int bi = 0, bf = 0;
        for (int i = lo + tid; i < hi; i += NTHR) {
            int v = ip[i];
            float f = fp[i];
            if (v != 0 && v != 1)          bi = 1;
            if (!(f == 0.0f || f == 1.0f)) bf = 1;
        }
        const int boi = __syncthreads_or(bi);
        const int bof = __syncthreads_or(bf);
        if (tid == 0) {
            if (boi) atomicOr(&g_badint, 1);
            if (bof) atomicOr(&g_badf, 1);
            __threadfence();
            if (atomicAdd(&g_sniff_done, 1) == NBLD - 1) {
                __threadfence();
                atomicExch(&g_mode_ready, 1);
            }
            while (atomicOr(&g_mode_ready, 0) == 0) __nanosleep(32);
            __threadfence();
        }
        __syncthreads();
        const bool u8mode = (g_badint != 0) && (g_badf != 0);
        const unsigned char* up = (const unsigned char*)wlraw;
        for (int c = b * NTHR + tid; c < NC; c += NBLD * NTHR) {
            unsigned m = 0;
#pragma unroll
            for (int l = 0; l < NL; ++l) {
                const bool on = u8mode ? (up[l * NC + c] != 0)
                                       : (ip[l * NC + c] != 0);
                if (on) m |= (1u << l);
            }
            if (m) {
                int p = atomicAdd(&g_wl_count, 1);
                if (p < MAXWL) {
                    g_wl_idx[p]  = c;
                    g_wl_mask[p] = (unsigned char)m;
                }
            }
        }
        __syncthreads();
        if (tid == 0) {
            __threadfence();
            if (atomicAdd(&g_wl_done, 1) == NBLD - 1) {
                __threadfence();
                atomicExch(&g_wl_ready, 1);
            }
        }
        return;                                    // builders done
    }

    // ================= row blocks: RPB rows sequentially ===================
    const int rb0 = (b - NBLD) * RPB;
    float x11v[RPB];

    for (int rr = 0; rr < RPB; ++rr) {
        const int rb = rb0 + rr;
        const float* xr = x + (size_t)rb * NC;

        // ---- stream: 4x float4 batched loads, per-thread top-3 ----
        float t0 = -INFINITY, t1 = -INFINITY, t2 = -INFINITY;

        const int a0   = (-rb) & 3;               // peel to 16B alignment
        const int n4   = (NC - a0) >> 2;
        const int tcnt = (NC - a0) & 3;
        const float4* xr4 = (const float4*)(xr + a0);

        if (tid < a0)   top3_ins(__ldg(xr + tid), t0, t1, t2);
        if (tid < tcnt) top3_ins(__ldg(xr + a0 + 4 * n4 + tid), t0, t1, t2);

        for (int base = 0; base < n4; base += NTHR * 4) {
            float4 q[4];
            bool   v[4];
#pragma unroll
            for (int u = 0; u < 4; ++u) {
                const int j = base + u * NTHR + tid;
                v[u] = (j < n4);
                if (v[u]) q[u] = __ldg(xr4 + j);
            }
#pragma unroll
            for (int u = 0; u < 4; ++u) {
                if (v[u]) {
                    top3_ins(q[u].x, t0, t1, t2); top3_ins(q[u].y, t0, t1, t2);
                    top3_ins(q[u].z, t0, t1, t2); top3_ins(q[u].w, t0, t1, t2);
                }
            }
        }

        // block max of t2 (validity bound)
        {
            float m = t2;
#pragma unroll
            for (int s = 16; s > 0; s >>= 1)
                m = fmaxf(m, __shfl_xor_sync(0xffffffffu, m, s));
            if ((tid & 31) == 0) s_fw[tid >> 5] = m;
        }
        s_keys[tid]            = f2k(__float_as_uint(t0));
        s_keys[NTHR + tid]     = f2k(__float_as_uint(t1));
        s_keys[2 * NTHR + tid] = f2k(__float_as_uint(t2));
        // zero level-0 bins (2048)
#pragma unroll
        for (int i = 0; i < 8; ++i) s_big[tid * 8 + i] = 0;
        __syncthreads();

        float maxt2 = s_fw[0];
#pragma unroll
        for (int w = 1; w < NTHR / 32; ++w) maxt2 = fmaxf(maxt2, s_fw[w]);
        const unsigned maxt2k = f2k(__float_as_uint(maxt2));

        // ---- flattened select: one 11-bit histogram over 768 keys ----
#pragma unroll
        for (int r = 0; r < 3; ++r)
            atomicAdd(&s_big[s_keys[r * NTHR + tid] >> 21], 1u);
        __syncthreads();
        unsigned want = 11;
        pick8(s_big, s_wsum, &s_bin, &s_want, &s_cnt, want, tid);
        const unsigned bin11 = s_bin;
        want = s_want;
        if (tid == 0) s_ncand = 0;
        __syncthreads();
        // collect the cnt keys in that bin (cnt <= 768 <= CAP)
#pragma unroll
        for (int r = 0; r < 3; ++r) {
            const unsigned k = s_keys[r * NTHR + tid];
            if ((k >> 21) == bin11) s_big[atomicAdd(&s_ncand, 1u)] = k;
        }
        __syncthreads();
        // exact rank-select among candidates (ties safe)
        {
            const int n = (int)s_ncand;
            for (int i = tid; i < n; i += NTHR) {
                const unsigned kk = s_big[i];
                unsigned gt = 0, ge = 0;
                for (int j = 0; j < n; ++j) {
                    const unsigned u = s_big[j];
                    gt += (u > kk);
                    ge += (u >= kk);
                }
                if (gt < want && want <= ge) s_selk = kk;
            }
        }
        __syncthreads();
        unsigned key11 = s_selk;

        // ---- validity check / exact full-histogram fallback ----
        if (maxt2k > key11) {
            __syncthreads();
#pragma unroll
            for (int i = 0; i < CAP / NTHR; ++i) s_big[tid + i * NTHR] = 0;
            __syncthreads();
            for (int c = tid; c < NC; c += NTHR) {
                const unsigned key = f2k(__float_as_uint(__ldg(xr + c)));
                atomicAdd(&s_big[key >> 21], 1u);
            }
            __syncthreads();
            want = 11;
            pick8(s_big, s_wsum, &s_bin, &s_want, &s_cnt, want, tid);
            unsigned pfx   = s_bin;
            int      pbits = 11;
            unsigned cnt   = s_cnt;
            want = s_want;
            __syncthreads();
            while (cnt > CAP && pbits < 32) {
                const int nb = (32 - pbits < 8) ? (32 - pbits) : 8;
                if (tid < (1 << nb)) s_big[tid] = 0;
                __syncthreads();
                for (int c = tid; c < NC; c += NTHR) {
                    const unsigned key = f2k(__float_as_uint(__ldg(xr + c)));
                    if ((key >> (32 - pbits)) == pfx)
                        atomicAdd(&s_big[(key >> (32 - pbits - nb)) & ((1u << nb) - 1u)], 1u);
                }
                __syncthreads();
                pick1(s_big, 1 << nb, s_wsum, &s_bin, &s_want, &s_cnt, want, tid);
                pfx = (pfx << nb) | s_bin;
                pbits += nb;
                cnt  = s_cnt;
                want = s_want;
                __syncthreads();
            }
            if (pbits >= 32) {
                key11 = pfx;
            } else {
                if (tid == 0) s_ncand = 0;
                __syncthreads();
                for (int c = tid; c < NC; c += NTHR) {
                    const unsigned key = f2k(__float_as_uint(__ldg(xr + c)));
                    if ((key >> (32 - pbits)) == pfx) {
                        unsigned p = atomicAdd(&s_ncand, 1u);
                        if (p < CAP) s_big[p] = key;
                    }
                }
                __syncthreads();
                const int n = (int)s_ncand;
                for (int i = tid; i < n; i += NTHR) {
                    const unsigned kk = s_big[i];
                    unsigned gt = 0, ge = 0;
                    for (int j = 0; j < n; ++j) {
                        const unsigned u = s_big[j];
                        gt += (u > kk);
                        ge += (u >= kk);
                    }
                    if (gt < want && want <= ge) s_selk = kk;
                }
                __syncthreads();
                key11 = s_selk;
            }
        }
        x11v[rr] = k2f(key11);
        __syncthreads();                           // protect shared reuse next row
    }

    // ================= wait for whitelist (set long ago) ===================
    if (tid == 0) {
        while (atomicOr(&g_wl_ready, 0) == 0) __nanosleep(64);
        __threadfence();
    }
    __syncthreads();

    // ================= per-row whitelist gather + epilogue =================
    const int nwl = g_wl_count;
    for (int rr = 0; rr < RPB; ++rr) {
        const int rb = rb0 + rr;
        const float* xr = x + (size_t)rb * NC;
        const float* yr = y + (size_t)rb * NC;

        float lmax[NL];
#pragma unroll
        for (int l = 0; l < NL; ++l) lmax[l] = -1e30f;
        float    unf = -1e30f;
        unsigned pos = 0;

        for (int e = tid; e < nwl; e += NTHR) {
            const int      c  = g_wl_idx[e];
            const unsigned m  = g_wl_mask[e];
            const float    xv = __ldg(xr + c);
            const float    yv = __ldg(yr + c);
            unf = fmaxf(unf, xv);
            if (yv > 0.0f) pos |= m;
#pragma unroll
            for (int l = 0; l < NL; ++l)
                if (m & (1u << l)) lmax[l] = fmaxf(lmax[l], xv);
        }
#pragma unroll
        for (int s = 16; s > 0; s >>= 1) {
#pragma unroll
            for (int l = 0; l < NL; ++l)
                lmax[l] = fmaxf(lmax[l], __shfl_xor_sync(0xffffffffu, lmax[l], s));
            unf = fmaxf(unf, __shfl_xor_sync(0xffffffffu, unf, s));
            pos |= __shfl_xor_sync(0xffffffffu, pos, s);
        }
        const int warp = tid >> 5, lane = tid & 31;
        if (lane == 0) {
#pragma unroll
            for (int l = 0; l < NL; ++l) s_lmax[warp][l] = lmax[l];
            s_un[warp] = unf;
            s_pb[warp] = pos;
        }
        __syncthreads();

        if (tid == 0) {
#pragma unroll
            for (int w = 1; w < NTHR / 32; ++w) {
#pragma unroll
                for (int l = 0; l < NL; ++l) lmax[l] = fmaxf(lmax[l], s_lmax[w][l]);
                unf = fmaxf(unf, s_un[w]);
                pos |= s_pb[w];
            }

            const float thres = fmaxf(sigmoidf_(x11v[rr]), 0.5f);  // ALPHA_OTHER

            float cx = -1e30f, ix = -1e30f;
#pragma unroll
            for (int l = 0; l < NL; ++l) {
                if (pos & (1u << l)) cx = fmaxf(cx, lmax[l]);
                else                 ix = fmaxf(ix, lmax[l]);
            }

            float x1, x2, coef;
            if (pos) {                              // any_correct
                x1   = sigmoidf_(cx);
                x2   = fmaxf(sigmoidf_(ix), thres); // covers any_incorrect branch
                coef = 1.0f;
            } else {
                x1   = thres;
                x2   = sigmoidf_(unf);
                coef = 0.5f;                        // 1 - ALPHA
            }
            const float d    = x2 - x1 + 0.1f;      // ALPHA1
            const float rank = (d > 0.0f ? 2.0f : 1.0f) * sigmoidf_(10.0f * d);
            g_row_val[rb] = coef * rank;
        }
        __syncthreads();
    }

    // ================= completion + last-block mean ========================
    if (tid == 0) {
        __threadfence();
        const int t = atomicAdd(&g_done, RPB);
        s_last = (t == BATCH - RPB);
    }
    __syncthreads();

    if (s_last) {
        float* s_red = (float*)s_big;
        float acc = 0.0f;
        for (int i = tid; i < BATCH; i += NTHR) acc += g_row_val[i];
        s_red[tid] = acc;
        __syncthreads();
        for (int off = NTHR / 2; off > 0; off >>= 1) {
            if (tid < off) s_red[tid] += s_red[tid + off];
            __syncthreads();
        }
        if (tid == 0) {
            out[0]       = s_red[0] * (1.0f / (float)BATCH);
            g_done       = 0;
            g_wl_count   = 0;
            g_wl_done    = 0;
            g_wl_ready   = 0;
            g_badint     = 0;
            g_badf       = 0;
            g_sniff_done = 0;
            g_mode_ready = 0;
        }
    }
}

extern "C" void kernel_launch(void* const* d_in, const int* in_sizes, int n_in,
                              void* d_out, int out_size) {
    const float* x  = (const float*)d_in[0];
    const float* y  = (const float*)d_in[1];
    // d_in[2] = y_neg: never affects the result, never read.
    const void*  wl = d_in[3];

    row_kernel<<<BATCH / RPB + NBLD, NTHR>>>(x, y, wl, (float*)d_out);
}

// round 17
// speedup vs baseline: 1.4031x; 1.4031x over previous
#include <cuda_runtime.h>
#include <math.h>

#define BATCH 2048
#define NC    9605
#define NL    8
#define MAXWL 512
#define NTHR  256
#define NBLD  32           // dedicated builder blocks (exit after building)
#define NCAND (3 * NTHR)   // 768-key per-thread top-3 union
#define CAP   2048         // level-0 bins / fallback hist / candidate buffer

__device__ int           g_wl_count;   // all zero-init; reset by last row block
__device__ int           g_wl_idx[MAXWL];
__device__ unsigned char g_wl_mask[MAXWL];
__device__ float         g_row_val[BATCH];
__device__ int           g_done;
__device__ int           g_wl_done;
__device__ int           g_wl_ready;
__device__ int           g_badint, g_badf;
__device__ int           g_sniff_done;
__device__ int           g_mode_ready;

__device__ __forceinline__ float sigmoidf_(float v) {
    return 1.0f / (1.0f + expf(-v));   // v = -1e30 -> 0 (correct)
}
__device__ __forceinline__ unsigned f2k(unsigned u) {          // monotone float->uint
    return (u & 0x80000000u) ? ~u : (u | 0x80000000u);
}
__device__ __forceinline__ float k2f(unsigned k) {
    return (k & 0x80000000u) ? __uint_as_float(k ^ 0x80000000u)
                             : __uint_as_float(~k);
}
// branchless sorted top-3 insert (6 ops, no branches)
__device__ __forceinline__ void top3_ins(float v, float& t0, float& t1, float& t2) {
    float m0  = fmaxf(t0, v);
    float mn0 = fminf(t0, v);
    float m1  = fmaxf(t1, mn0);
    float mn1 = fminf(t1, mn0);
    t2 = fmaxf(t2, mn1);
    t0 = m0; t1 = m1;
}

// pick8: suffix-select over 2048 bins (thread t owns bins [8t,8t+8)).
__device__ __forceinline__ void pick8(const unsigned* __restrict__ hist,
                                      unsigned* __restrict__ wsum,
                                      unsigned* __restrict__ sb,
                                      unsigned* __restrict__ sw,
                                      unsigned* __restrict__ sc,
                                      unsigned want, int tid) {
    unsigned v[8];
    unsigned tot = 0;
#pragma unroll
    for (int i = 0; i < 8; ++i) { v[i] = hist[tid * 8 + i]; tot += v[i]; }
    unsigned incl = tot;
#pragma unroll
    for (int d = 1; d < 32; d <<= 1) {
        unsigned n = __shfl_down_sync(0xffffffffu, incl, d);
        if ((tid & 31) + d < 32) incl += n;
    }
    if ((tid & 31) == 0) wsum[tid >> 5] = incl;
    __syncthreads();
    unsigned above = incl - tot;
#pragma unroll
    for (int w = 0; w < NTHR / 32; ++w)
        if (w > (tid >> 5)) above += wsum[w];
    unsigned suf = above;
#pragma unroll
    for (int j = 7; j >= 0; --j) {
        unsigned nsuf = suf + v[j];
        if (suf < want && want <= nsuf) {
            *sb = (unsigned)(tid * 8 + j); *sw = want - suf; *sc = v[j];
        }
        suf = nsuf;
    }
    __syncthreads();
}

// pick1: suffix-select over <=256 bins (thread t owns bin t). (fallback)
__device__ __forceinline__ void pick1(const unsigned* __restrict__ hist, int nbins,
                                      unsigned* __restrict__ wsum,
                                      unsigned* __restrict__ sb,
                                      unsigned* __restrict__ sw,
                                      unsigned* __restrict__ sc,
                                      unsigned want, int tid) {
    unsigned v = (tid < nbins) ? hist[tid] : 0u;
    unsigned incl = v;
#pragma unroll
    for (int d = 1; d < 32; d <<= 1) {
        unsigned n = __shfl_down_sync(0xffffffffu, incl, d);
        if ((tid & 31) + d < 32) incl += n;
    }
    if ((tid & 31) == 0) wsum[tid >> 5] = incl;
    __syncthreads();
    unsigned above = incl - v;
#pragma unroll
    for (int w = 0; w < NTHR / 32; ++w)
        if (w > (tid >> 5)) above += wsum[w];
    if (above < want && want <= above + v) { *sb = (unsigned)tid; *sw = want - above; *sc = v; }
    __syncthreads();
}

// ---------------------------------------------------------------------------
// Single kernel, grid = NBLD + BATCH (round-15 structure).
//  Blocks 0..NBLD-1: dedicated builders (distributed dtype sniff + stripe
//  compaction), then EXIT — off the row critical path.
//  Row blocks (one row each): float4 x4 stream + per-thread top-3; FLATTENED
//  select (one 11-bit histogram over the 768-key union + candidate collect +
//  exact rank-select); conservative validity bound with exact full-histogram
//  fallback; post-select wl spin; gather; epilogue; last row block does the
//  deterministic mean + state reset.
// ---------------------------------------------------------------------------
__global__ void __launch_bounds__(NTHR, 8)
row_kernel(const float* __restrict__ x, const float* __restrict__ y,
           const void* __restrict__ wlraw, float* __restrict__ out) {
    __shared__ unsigned s_keys[NCAND];
    __shared__ unsigned s_big[CAP];               // lvl0 bins / cands / fallback / mean
    __shared__ unsigned s_wsum[NTHR / 32];
    __shared__ float    s_fw[NTHR / 32];
    __shared__ unsigned s_bin, s_want, s_cnt;
    __shared__ unsigned s_ncand, s_selk;
    __shared__ float    s_lmax[NTHR / 32][NL];
    __shared__ float    s_un[NTHR / 32];
    __shared__ unsigned s_pb[NTHR / 32];
    __shared__ int      s_last;

    const int b   = blockIdx.x;
    const int tid = threadIdx.x;

    // ================= builder blocks: build whitelist, exit ===============
    if (b < NBLD) {
        const int NQ    = (NL * NC) / 4;          // safe 4B slots under any dtype
        const int chunk = (NQ + NBLD - 1) / NBLD;
        const int lo    = b * chunk;
        const int hi    = (lo + chunk < NQ) ? lo + chunk : NQ;
        const int*   ip = (const int*)wlraw;
        const float* fp = (const float*)wlraw;
        int bi = 0, bf = 0;
        for (int i = lo + tid; i < hi; i += NTHR) {
            int v = ip[i];
            float f = fp[i];
            if (v != 0 && v != 1)          bi = 1;
            if (!(f == 0.0f || f == 1.0f)) bf = 1;
        }
        const int boi = __syncthreads_or(bi);
        const int bof = __syncthreads_or(bf);
        if (tid == 0) {
            if (boi) atomicOr(&g_badint, 1);
            if (bof) atomicOr(&g_badf, 1);
            __threadfence();
            if (atomicAdd(&g_sniff_done, 1) == NBLD - 1) {
                __threadfence();
                atomicExch(&g_mode_ready, 1);
            }
            while (atomicOr(&g_mode_ready, 0) == 0) __nanosleep(32);
            __threadfence();
        }
        __syncthreads();
        const bool u8mode = (g_badint != 0) && (g_badf != 0);
        const unsigned char* up = (const unsigned char*)wlraw;
        for (int c = b * NTHR + tid; c < NC; c += NBLD * NTHR) {
            unsigned m = 0;
#pragma unroll
            for (int l = 0; l < NL; ++l) {
                const bool on = u8mode ? (up[l * NC + c] != 0)
                                       : (ip[l * NC + c] != 0);
                if (on) m |= (1u << l);
            }
            if (m) {
                int p = atomicAdd(&g_wl_count, 1);
                if (p < MAXWL) {
                    g_wl_idx[p]  = c;
                    g_wl_mask[p] = (unsigned char)m;
                }
            }
        }
        __syncthreads();
        if (tid == 0) {
            __threadfence();
            if (atomicAdd(&g_wl_done, 1) == NBLD - 1) {
                __threadfence();
                atomicExch(&g_wl_ready, 1);
            }
        }
        return;                                    // builders done
    }

    // ================= row block: one row =================================
    const int rb = b - NBLD;
    const float* xr = x + (size_t)rb * NC;
    const float* yr = y + (size_t)rb * NC;

    // ====== phase A: stream, 4x float4 batched loads, per-thread top-3 =====
    float t0 = -INFINITY, t1 = -INFINITY, t2 = -INFINITY;

    const int a0   = (-rb) & 3;                   // peel to 16B alignment
    const int n4   = (NC - a0) >> 2;
    const int tcnt = (NC - a0) & 3;
    const float4* xr4 = (const float4*)(xr + a0);

    if (tid < a0)   top3_ins(__ldg(xr + tid), t0, t1, t2);
    if (tid < tcnt) top3_ins(__ldg(xr + a0 + 4 * n4 + tid), t0, t1, t2);

    for (int base = 0; base < n4; base += NTHR * 4) {
        float4 q[4];
        bool   v[4];
#pragma unroll
        for (int u = 0; u < 4; ++u) {
            const int j = base + u * NTHR + tid;
            v[u] = (j < n4);
            if (v[u]) q[u] = __ldg(xr4 + j);
        }
#pragma unroll
        for (int u = 0; u < 4; ++u) {
            if (v[u]) {
                top3_ins(q[u].x, t0, t1, t2); top3_ins(q[u].y, t0, t1, t2);
                top3_ins(q[u].z, t0, t1, t2); top3_ins(q[u].w, t0, t1, t2);
            }
        }
    }

    // block max of t2 (validity bound)
    {
        float m = t2;
#pragma unroll
        for (int s = 16; s > 0; s >>= 1)
            m = fmaxf(m, __shfl_xor_sync(0xffffffffu, m, s));
        if ((tid & 31) == 0) s_fw[tid >> 5] = m;
    }
    s_keys[tid]            = f2k(__float_as_uint(t0));
    s_keys[NTHR + tid]     = f2k(__float_as_uint(t1));
    s_keys[2 * NTHR + tid] = f2k(__float_as_uint(t2));
    // zero level-0 bins (2048)
#pragma unroll
    for (int i = 0; i < 8; ++i) s_big[tid * 8 + i] = 0;
    __syncthreads();

    float maxt2 = s_fw[0];
#pragma unroll
    for (int w = 1; w < NTHR / 32; ++w) maxt2 = fmaxf(maxt2, s_fw[w]);
    const unsigned maxt2k = f2k(__float_as_uint(maxt2));

    // ====== flattened select: one 11-bit histogram over 768 keys ===========
#pragma unroll
    for (int r = 0; r < 3; ++r)
        atomicAdd(&s_big[s_keys[r * NTHR + tid] >> 21], 1u);
    __syncthreads();
    unsigned want = 11;
    pick8(s_big, s_wsum, &s_bin, &s_want, &s_cnt, want, tid);
    const unsigned bin11 = s_bin;
    want = s_want;
    if (tid == 0) s_ncand = 0;
    __syncthreads();
    // collect the cnt keys in that bin (cnt <= 768 <= CAP)
#pragma unroll
    for (int r = 0; r < 3; ++r) {
        const unsigned k = s_keys[r * NTHR + tid];
        if ((k >> 21) == bin11) s_big[atomicAdd(&s_ncand, 1u)] = k;
    }
    __syncthreads();
    // exact rank-select among candidates (ties safe)
    {
        const int n = (int)s_ncand;
        for (int i = tid; i < n; i += NTHR) {
            const unsigned kk = s_big[i];
            unsigned gt = 0, ge = 0;
            for (int j = 0; j < n; ++j) {
                const unsigned u = s_big[j];
                gt += (u > kk);
                ge += (u >= kk);
            }
            if (gt < want && want <= ge) s_selk = kk;
        }
    }
    __syncthreads();
    unsigned key11 = s_selk;

    // ================= validity check / exact fallback =====================
    if (maxt2k > key11) {
        __syncthreads();
#pragma unroll
        for (int i = 0; i < CAP / NTHR; ++i) s_big[tid + i * NTHR] = 0;
        __syncthreads();
        for (int c = tid; c < NC; c += NTHR) {
            const unsigned key = f2k(__float_as_uint(__ldg(xr + c)));
            atomicAdd(&s_big[key >> 21], 1u);
        }
        __syncthreads();
        want = 11;
        pick8(s_big, s_wsum, &s_bin, &s_want, &s_cnt, want, tid);
        unsigned pfx   = s_bin;
        int      pbits = 11;
        unsigned cnt   = s_cnt;
        want = s_want;
        __syncthreads();
        while (cnt > CAP && pbits < 32) {
            const int nb = (32 - pbits < 8) ? (32 - pbits) : 8;
            if (tid < (1 << nb)) s_big[tid] = 0;
            __syncthreads();
            for (int c = tid; c < NC; c += NTHR) {
                const unsigned key = f2k(__float_as_uint(__ldg(xr + c)));
                if ((key >> (32 - pbits)) == pfx)
                    atomicAdd(&s_big[(key >> (32 - pbits - nb)) & ((1u << nb) - 1u)], 1u);
            }
            __syncthreads();
            pick1(s_big, 1 << nb, s_wsum, &s_bin, &s_want, &s_cnt, want, tid);
            pfx = (pfx << nb) | s_bin;
            pbits += nb;
            cnt  = s_cnt;
            want = s_want;
            __syncthreads();
        }
        if (pbits >= 32) {
            key11 = pfx;
        } else {
            if (tid == 0) s_ncand = 0;
            __syncthreads();
            for (int c = tid; c < NC; c += NTHR) {
                const unsigned key = f2k(__float_as_uint(__ldg(xr + c)));
                if ((key >> (32 - pbits)) == pfx) {
                    unsigned p = atomicAdd(&s_ncand, 1u);
                    if (p < CAP) s_big[p] = key;
                }
            }
            __syncthreads();
            const int n = (int)s_ncand;
            for (int i = tid; i < n; i += NTHR) {
                const unsigned kk = s_big[i];
                unsigned gt = 0, ge = 0;
                for (int j = 0; j < n; ++j) {
                    const unsigned u = s_big[j];
                    gt += (u > kk);
                    ge += (u >= kk);
                }
                if (gt < want && want <= ge) s_selk = kk;
            }
            __syncthreads();
            key11 = s_selk;
        }
    }
    const float x11 = k2f(key11);

    // ================= wait for whitelist (set long ago) ===================
    if (tid == 0) {
        while (atomicOr(&g_wl_ready, 0) == 0) __nanosleep(64);
        __threadfence();
    }
    __syncthreads();

    // ================= whitelist gather (x from L2, y sparse) ==============
    const int nwl = g_wl_count;
    float lmax[NL];
#pragma unroll
    for (int l = 0; l < NL; ++l) lmax[l] = -1e30f;
    float    unf = -1e30f;
    unsigned pos = 0;

    for (int e = tid; e < nwl; e += NTHR) {
        const int      c  = g_wl_idx[e];
        const unsigned m  = g_wl_mask[e];
        const float    xv = __ldg(xr + c);
        const float    yv = __ldg(yr + c);
        unf = fmaxf(unf, xv);
        if (yv > 0.0f) pos |= m;
#pragma unroll
        for (int l = 0; l < NL; ++l)
            if (m & (1u << l)) lmax[l] = fmaxf(lmax[l], xv);
    }
#pragma unroll
    for (int s = 16; s > 0; s >>= 1) {
#pragma unroll
        for (int l = 0; l < NL; ++l)
            lmax[l] = fmaxf(lmax[l], __shfl_xor_sync(0xffffffffu, lmax[l], s));
        unf = fmaxf(unf, __shfl_xor_sync(0xffffffffu, unf, s));
        pos |= __shfl_xor_sync(0xffffffffu, pos, s);
    }
    const int warp = tid >> 5, lane = tid & 31;
    if (lane == 0) {
#pragma unroll
        for (int l = 0; l < NL; ++l) s_lmax[warp][l] = lmax[l];
        s_un[warp] = unf;
        s_pb[warp] = pos;
    }
    __syncthreads();

    if (tid == 0) {
#pragma unroll
        for (int w = 1; w < NTHR / 32; ++w) {
#pragma unroll
            for (int l = 0; l < NL; ++l) lmax[l] = fmaxf(lmax[l], s_lmax[w][l]);
            unf = fmaxf(unf, s_un[w]);
            pos |= s_pb[w];
        }

        const float thres = fmaxf(sigmoidf_(x11), 0.5f);   // ALPHA_OTHER

        float cx = -1e30f, ix = -1e30f;
#pragma unroll
        for (int l = 0; l < NL; ++l) {
            if (pos & (1u << l)) cx = fmaxf(cx, lmax[l]);
            else                 ix = fmaxf(ix, lmax[l]);
        }

        float x1, x2, coef;
        if (pos) {                                  // any_correct
            x1   = sigmoidf_(cx);
            x2   = fmaxf(sigmoidf_(ix), thres);     // covers any_incorrect branch
            coef = 1.0f;
        } else {
            x1   = thres;
            x2   = sigmoidf_(unf);
            coef = 0.5f;                            // 1 - ALPHA
        }
        const float d    = x2 - x1 + 0.1f;          // ALPHA1
        const float rank = (d > 0.0f ? 2.0f : 1.0f) * sigmoidf_(10.0f * d);

        g_row_val[rb] = coef * rank;
        __threadfence();
        const int t = atomicAdd(&g_done, 1);
        s_last = (t == BATCH - 1);
    }
    __syncthreads();

    // ================= last row block: mean + state reset ==================
    if (s_last) {
        float* s_red = (float*)s_big;
        float acc = 0.0f;
        for (int i = tid; i < BATCH; i += NTHR) acc += g_row_val[i];
        s_red[tid] = acc;
        __syncthreads();
        for (int off = NTHR / 2; off > 0; off >>= 1) {
            if (tid < off) s_red[tid] += s_red[tid + off];
            __syncthreads();
        }
        if (tid == 0) {
            out[0]       = s_red[0] * (1.0f / (float)BATCH);
            g_done       = 0;
            g_wl_count   = 0;
            g_wl_done    = 0;
            g_wl_ready   = 0;
            g_badint     = 0;
            g_badf       = 0;
            g_sniff_done = 0;
            g_mode_ready = 0;
        }
    }
}

extern "C" void kernel_launch(void* const* d_in, const int* in_sizes, int n_in,
                              void* d_out, int out_size) {
    const float* x  = (const float*)d_in[0];
    const float* y  = (const float*)d_in[1];
    // d_in[2] = y_neg: never affects the result, never read.
    const void*  wl = d_in[3];

    row_kernel<<<BATCH + NBLD, NTHR>>>(x, y, wl, (float*)d_out);
}